// round 12
// baseline (speedup 1.0000x reference)
#include <cuda_runtime.h>
#include <cooperative_groups.h>
namespace cg = cooperative_groups;

// Problem constants (fixed shapes from the reference setup)
#define NB   16      // batch
#define NT   128     // time
#define NHWC 25088   // 56*56*8 floats per frame
#define NS4  6272    // NHWC / 4 (float4 strips per frame)
#define NC   8       // channels
#define KCH  2       // time chunks
#define TC   (NT / KCH)             // 64 frames per chunk
#define BT   224     // block threads; NS4 = 28 * 224 exactly
#define NW   (BT / 32)              // 7 warps
#define NBLK_S (NS4 / BT)           // 28 blocks over the spatial strip
#define SLOTS_PER_B (KCH * NBLK_S)  // 56
#define NBLKS  (NB * SLOTS_PER_B)   // 896 total blocks (<= 1036 co-resident cap)
#define NFLD   17                   // 8 act + 8 tot + 1 ttv

// Scratch (no device allocation allowed -> __device__ globals).
// FIELD-MAJOR layout: g_part[field][slot] -> coalesced tail reads.
// Every block writes all its fields every launch => no zeroing needed.
__device__ float g_part[NFLD][NBLKS];

__global__ __launch_bounds__(BT) void fused_coop_kernel(const float4* __restrict__ x,
                                                        const int*   __restrict__ length,
                                                        const float* __restrict__ count,
                                                        float*       __restrict__ out) {
    const int s4    = blockIdx.x * BT + threadIdx.x;   // always < NS4
    const int chunk = blockIdx.y;
    const int b     = blockIdx.z;
    const int len   = __ldg(&length[b]);
    const int t0    = chunk * TC;
    const float4* base = x + (size_t)b * NT * NS4 + s4;

    float ax = 0.f, ay = 0.f, az = 0.f, aw = 0.f;   // active sums (4 channels)
    float tx = 0.f, ty = 0.f, tz = 0.f, tw = 0.f;   // total sums
    float ttv = 0.f;
    float px = 0.f, py = 0.f, pz = 0.f, pw = 0.f;   // previous masked frame

    if (t0 > 0 && (t0 - 1) < len) {
        float4 p = __ldcs(&base[(size_t)(t0 - 1) * NS4]);
        px = p.x; py = p.y; pz = p.z; pw = p.w;
    }
    #pragma unroll 8
    for (int t = t0; t < t0 + TC; ++t) {
        float4 v = __ldcs(&base[(size_t)t * NS4]);
        tx += v.x; ty += v.y; tz += v.z; tw += v.w;
        float cx, cy, cz, cw;
        if (t < len) {
            cx = v.x; cy = v.y; cz = v.z; cw = v.w;
            ax += v.x; ay += v.y; az += v.z; aw += v.w;
        } else {
            cx = 0.f; cy = 0.f; cz = 0.f; cw = 0.f;
        }
        if (t > 0) {   // skip only the global t=0 (chunk 0, first iter)
            ttv += fabsf(cx - px) + fabsf(cy - py) + fabsf(cz - pz) + fabsf(cw - pw);
        }
        px = cx; py = cy; pz = cz; pw = cw;
    }

    // --- block reduction ---
    #pragma unroll
    for (int m = 16; m >= 1; m >>= 1)
        ttv += __shfl_xor_sync(0xffffffffu, ttv, m);
    // Parity-preserving reduce: even lanes hold channels 0-3, odd lanes 4-7
    #pragma unroll
    for (int m = 2; m <= 16; m <<= 1) {
        ax += __shfl_xor_sync(0xffffffffu, ax, m);
        ay += __shfl_xor_sync(0xffffffffu, ay, m);
        az += __shfl_xor_sync(0xffffffffu, az, m);
        aw += __shfl_xor_sync(0xffffffffu, aw, m);
        tx += __shfl_xor_sync(0xffffffffu, tx, m);
        ty += __shfl_xor_sync(0xffffffffu, ty, m);
        tz += __shfl_xor_sync(0xffffffffu, tz, m);
        tw += __shfl_xor_sync(0xffffffffu, tw, m);
    }

    __shared__ float sh_a[NW][NC];
    __shared__ float sh_t[NW][NC];
    __shared__ float sh_v[NW];
    const int w = threadIdx.x >> 5, lane = threadIdx.x & 31;
    if (lane == 0) {
        sh_a[w][0] = ax; sh_a[w][1] = ay; sh_a[w][2] = az; sh_a[w][3] = aw;
        sh_t[w][0] = tx; sh_t[w][1] = ty; sh_t[w][2] = tz; sh_t[w][3] = tw;
        sh_v[w] = ttv;
    } else if (lane == 1) {
        sh_a[w][4] = ax; sh_a[w][5] = ay; sh_a[w][6] = az; sh_a[w][7] = aw;
        sh_t[w][4] = tx; sh_t[w][5] = ty; sh_t[w][6] = tz; sh_t[w][7] = tw;
    }
    __syncthreads();

    const int slot = (b * KCH + chunk) * NBLK_S + blockIdx.x;
    if (threadIdx.x < NC) {
        const int c = threadIdx.x;
        float sa = 0.f, st = 0.f;
        #pragma unroll
        for (int w2 = 0; w2 < NW; ++w2) { sa += sh_a[w2][c]; st += sh_t[w2][c]; }
        g_part[c][slot]      = sa;
        g_part[NC + c][slot] = st;
    } else if (threadIdx.x == NC) {
        float s = 0.f;
        #pragma unroll
        for (int w2 = 0; w2 < NW; ++w2) s += sh_v[w2];
        g_part[16][slot] = s;
    }

    // --- grid-wide barrier (HW cooperative sync; memory visible after) ---
    cg::this_grid().sync();

    // --- tail: one block per batch ---
    if (blockIdx.x != 0 || chunk != 0) return;

    __shared__ float sh_fld[NFLD];
    __shared__ float sh_tv[NW];

    // Fields: warp w reduces rows {w, w+7, w+14} over this batch's 56 slots
    // (coalesced: consecutive lanes -> consecutive slots). 56 = 32 + 24.
    for (int r = w; r < NFLD; r += NW) {
        const float* p = &g_part[r][b * SLOTS_PER_B];
        float acc = __ldcg(&p[lane]);
        if (lane < 24) acc += __ldcg(&p[32 + lane]);
        #pragma unroll
        for (int m = 16; m >= 1; m >>= 1)
            acc += __shfl_xor_sync(0xffffffffu, acc, m);
        if (lane == 0) sh_fld[r] = acc;
    }

    // Global TTV: sum the whole 896-entry ttv row (same value for all batches).
    {
        float v = 0.f;
        #pragma unroll
        for (int k = 0; k < NBLKS / BT; ++k)
            v += __ldcg(&g_part[16][k * BT + threadIdx.x]);
        #pragma unroll
        for (int m = 16; m >= 1; m >>= 1)
            v += __shfl_xor_sync(0xffffffffu, v, m);
        if (lane == 0) sh_tv[w] = v;
    }
    __syncthreads();

    if (threadIdx.x == 0) {
        float tv = 0.f;
        #pragma unroll
        for (int i = 0; i < NW; ++i) tv += sh_tv[i];
        float ah = 0.f, bh = 0.f;
        #pragma unroll
        for (int c = 0; c < NC; ++c) {
            const float aa = sh_fld[c];
            const float tt = sh_fld[NC + c];
            float e  = aa - __ldg(&count[b * NC + c]);
            float ae = fabsf(e);
            ah += (ae <= 1.f) ? 0.5f * e * e : (ae - 0.5f);
            float eb  = tt - aa;
            float aeb = fabsf(eb);
            bh += (aeb <= 1.f) ? 0.5f * eb * eb : (aeb - 0.5f);
        }
        out[b] = ah * (1.f / NC) + bh * (1.f / NC) + tv * 0.1f;
    }
}

extern "C" void kernel_launch(void* const* d_in, const int* in_sizes, int n_in,
                              void* d_out, int out_size) {
    const float* cam    = (const float*)d_in[0];
    const float* count  = (const float*)d_in[1];
    const int*   length = (const int*)d_in[2];
    float*       out    = (float*)d_out;

    const float4* xv = (const float4*)cam;
    void* args[] = { (void*)&xv, (void*)&length, (void*)&count, (void*)&out };
    dim3 grid(NBLK_S, KCH, NB);   // 28 x 2 x 16 = 896 blocks (co-resident cap 1036)
    dim3 block(BT);
    cudaLaunchCooperativeKernel((const void*)fused_coop_kernel, grid, block, args, 0, (cudaStream_t)0);
}

// round 13
// speedup vs baseline: 1.0621x; 1.0621x over previous
#include <cuda_runtime.h>

// Problem constants (fixed shapes from the reference setup)
#define NB   16      // batch
#define NT   128     // time
#define NHWC 25088   // 56*56*8 floats per frame
#define NS4  6272    // NHWC / 4 (float4 strips per frame)
#define NC   8       // channels
#define KCH  2       // time chunks
#define TC   (NT / KCH)             // 64 frames per chunk
#define BT   224                    // block threads; NS4 = 28 * 224 exactly
#define NW   (BT / 32)              // 7 warps
#define NBLK_S (NS4 / BT)           // 28 blocks over the spatial strip

// Accumulators (no device allocation allowed -> __device__ globals).
// Zero at module load; final_kernel RESETS them to zero every launch, so the
// zero-invariant holds across the correctness run and every graph replay.
// fp64 atomics keep the 51M-term sums well inside the 1e-3 rel-err budget.
__device__ double g_act[NB * NC];
__device__ double g_tot[NB * NC];
__device__ double g_ttv;

__global__ __launch_bounds__(BT) void reduce_kernel(const float4* __restrict__ x,
                                                    const int* __restrict__ length) {
    // PDL trigger at start: the secondary launches/ramps during the stream and
    // HW-waits (cudaGridDependencySynchronize) for this grid's completion.
    cudaTriggerProgrammaticLaunchCompletion();

    const int s4    = blockIdx.x * BT + threadIdx.x;   // always < NS4
    const int chunk = blockIdx.y;
    const int b     = blockIdx.z;
    const int len   = __ldg(&length[b]);
    const int t0    = chunk * TC;
    const float4* base = x + (size_t)b * NT * NS4 + s4;

    float ax = 0.f, ay = 0.f, az = 0.f, aw = 0.f;   // active sums (4 channels)
    float tx = 0.f, ty = 0.f, tz = 0.f, tw = 0.f;   // total sums
    float ttv = 0.f;
    float px = 0.f, py = 0.f, pz = 0.f, pw = 0.f;   // previous masked frame

    if (t0 > 0 && (t0 - 1) < len) {
        float4 p = __ldcs(&base[(size_t)(t0 - 1) * NS4]);
        px = p.x; py = p.y; pz = p.z; pw = p.w;
    }
    #pragma unroll 8
    for (int t = t0; t < t0 + TC; ++t) {
        float4 v = __ldcs(&base[(size_t)t * NS4]);
        tx += v.x; ty += v.y; tz += v.z; tw += v.w;
        float cx, cy, cz, cw;
        if (t < len) {
            cx = v.x; cy = v.y; cz = v.z; cw = v.w;
            ax += v.x; ay += v.y; az += v.z; aw += v.w;
        } else {
            cx = 0.f; cy = 0.f; cz = 0.f; cw = 0.f;
        }
        if (t > 0) {   // skip only the global t=0 (chunk 0, first iter)
            ttv += fabsf(cx - px) + fabsf(cy - py) + fabsf(cz - pz) + fabsf(cw - pw);
        }
        px = cx; py = cy; pz = cz; pw = cw;
    }

    // --- block reduction ---
    #pragma unroll
    for (int m = 16; m >= 1; m >>= 1)
        ttv += __shfl_xor_sync(0xffffffffu, ttv, m);
    // Parity-preserving reduce: even lanes hold channels 0-3, odd lanes 4-7
    #pragma unroll
    for (int m = 2; m <= 16; m <<= 1) {
        ax += __shfl_xor_sync(0xffffffffu, ax, m);
        ay += __shfl_xor_sync(0xffffffffu, ay, m);
        az += __shfl_xor_sync(0xffffffffu, az, m);
        aw += __shfl_xor_sync(0xffffffffu, aw, m);
        tx += __shfl_xor_sync(0xffffffffu, tx, m);
        ty += __shfl_xor_sync(0xffffffffu, ty, m);
        tz += __shfl_xor_sync(0xffffffffu, tz, m);
        tw += __shfl_xor_sync(0xffffffffu, tw, m);
    }

    __shared__ float sh_a[NW][NC];
    __shared__ float sh_t[NW][NC];
    __shared__ float sh_v[NW];
    const int w = threadIdx.x >> 5, lane = threadIdx.x & 31;
    if (lane == 0) {
        sh_a[w][0] = ax; sh_a[w][1] = ay; sh_a[w][2] = az; sh_a[w][3] = aw;
        sh_t[w][0] = tx; sh_t[w][1] = ty; sh_t[w][2] = tz; sh_t[w][3] = tw;
        sh_v[w] = ttv;
    } else if (lane == 1) {
        sh_a[w][4] = ax; sh_a[w][5] = ay; sh_a[w][6] = az; sh_a[w][7] = aw;
        sh_t[w][4] = tx; sh_t[w][5] = ty; sh_t[w][6] = tz; sh_t[w][7] = tw;
    }
    __syncthreads();

    // Per-(b,c) fp64 atomic accumulation: 17 REDGs per block to 129 addresses.
    if (threadIdx.x < NC) {
        const int c = threadIdx.x;
        float sa = 0.f, st = 0.f;
        #pragma unroll
        for (int w2 = 0; w2 < NW; ++w2) { sa += sh_a[w2][c]; st += sh_t[w2][c]; }
        atomicAdd(&g_act[b * NC + c], (double)sa);
        atomicAdd(&g_tot[b * NC + c], (double)st);
    } else if (threadIdx.x == NC) {
        float s = 0.f;
        #pragma unroll
        for (int w2 = 0; w2 < NW; ++w2) s += sh_v[w2];
        atomicAdd(&g_ttv, (double)s);
    }
}

// PDL secondary: single tiny block. Reads the 129 fp64 accumulators, computes
// the Huber losses + ttv, writes out[0..15], then RESETS the accumulators to
// zero (restoring the invariant for the next replay -> deterministic).
__global__ __launch_bounds__(160) void final_kernel(const float* __restrict__ count,
                                                    float* __restrict__ out) {
    cudaGridDependencySynchronize();   // HW wait for primary grid completion

    __shared__ float sh_a[NB * NC];
    __shared__ float sh_t[NB * NC];
    __shared__ float sh_tv;

    const int i = threadIdx.x;
    if (i < NB * NC) {
        sh_a[i] = (float)g_act[i];
        sh_t[i] = (float)g_tot[i];
        g_act[i] = 0.0;   // reset for next replay
        g_tot[i] = 0.0;
    } else if (i == NB * NC) {
        sh_tv = (float)g_ttv * 0.1f;
        g_ttv = 0.0;
    }
    __syncthreads();

    if (i < NB) {
        const int b = i;
        float ah = 0.f, bh = 0.f;
        #pragma unroll
        for (int c = 0; c < NC; ++c) {
            const float aa = sh_a[b * NC + c];
            const float tt = sh_t[b * NC + c];
            float e  = aa - __ldg(&count[b * NC + c]);
            float ae = fabsf(e);
            ah += (ae <= 1.f) ? 0.5f * e * e : (ae - 0.5f);
            float eb  = tt - aa;
            float aeb = fabsf(eb);
            bh += (aeb <= 1.f) ? 0.5f * eb * eb : (aeb - 0.5f);
        }
        out[b] = ah * (1.f / NC) + bh * (1.f / NC) + sh_tv;
    }
}

extern "C" void kernel_launch(void* const* d_in, const int* in_sizes, int n_in,
                              void* d_out, int out_size) {
    const float* cam    = (const float*)d_in[0];
    const float* count  = (const float*)d_in[1];
    const int*   length = (const int*)d_in[2];
    float*       out    = (float*)d_out;

    dim3 grid(NBLK_S, KCH, NB);   // 28 x 2 x 16 = 896 blocks
    reduce_kernel<<<grid, BT>>>((const float4*)cam, length);

    cudaLaunchConfig_t cfg = {};
    cfg.gridDim  = dim3(1, 1, 1);
    cfg.blockDim = dim3(160, 1, 1);
    cfg.stream   = 0;
    cudaLaunchAttribute attrs[1];
    attrs[0].id = cudaLaunchAttributeProgrammaticStreamSerialization;
    attrs[0].val.programmaticStreamSerializationAllowed = 1;
    cfg.attrs    = attrs;
    cfg.numAttrs = 1;
    cudaLaunchKernelEx(&cfg, final_kernel, count, out);
}